// round 2
// baseline (speedup 1.0000x reference)
#include <cuda_runtime.h>
#include <math.h>

#define NN   100000
#define EE   1600000
#define TOTE 1700000   // E + N self loops
#define FIN  128
#define FHID 64
#define FOUT 40
#define KSTEPS 10
#define ALPHA 0.1f

// ---------------- scratch (static device globals; no allocation) ----------------
__device__ int    g_cnt[NN];
__device__ int    g_rowptr[NN + 1];
__device__ int    g_pos[NN];
__device__ float  g_dinv[NN];
__device__ float2 g_edata[TOTE];          // {src (bits), weight=0.9*dinv[s]*dinv[d]}
__device__ int    g_blksums[128];
__device__ float  g_h0[NN * FHID];        // teleport target (also gemm output)
__device__ float  g_bufA[NN * FHID];
__device__ float  g_bufB[NN * FHID];

// ---------------- CSR build ----------------
__global__ void k_init_cnt() {
    int i = blockIdx.x * blockDim.x + threadIdx.x;
    if (i < NN) g_cnt[i] = 1;            // self loop
}

__global__ void k_deg(const int* __restrict__ dst) {
    int e = blockIdx.x * blockDim.x + threadIdx.x;
    if (e < EE) atomicAdd(&g_cnt[dst[e]], 1);
}

__global__ void k_dinv() {
    int i = blockIdx.x * blockDim.x + threadIdx.x;
    if (i < NN) g_dinv[i] = rsqrtf((float)g_cnt[i]);
}

__global__ void k_scan1() {              // 98 blocks x 1024
    __shared__ int sh[1024];
    int t = threadIdx.x, b = blockIdx.x;
    int i = b * 1024 + t;
    int v = (i < NN) ? g_cnt[i] : 0;
    sh[t] = v;
    __syncthreads();
    for (int off = 1; off < 1024; off <<= 1) {
        int add = (t >= off) ? sh[t - off] : 0;
        __syncthreads();
        sh[t] += add;
        __syncthreads();
    }
    if (i < NN) g_rowptr[i] = sh[t] - v;   // exclusive within block
    if (t == 1023) g_blksums[b] = sh[1023];
}

__global__ void k_scan2() {              // 1 block x 128
    __shared__ int sh[128];
    int t = threadIdx.x;
    int v = (t < 98) ? g_blksums[t] : 0;
    sh[t] = v;
    __syncthreads();
    for (int off = 1; off < 128; off <<= 1) {
        int add = (t >= off) ? sh[t - off] : 0;
        __syncthreads();
        sh[t] += add;
        __syncthreads();
    }
    g_blksums[t] = sh[t] - v;              // exclusive block offsets
}

__global__ void k_scan3() {
    int i = blockIdx.x * blockDim.x + threadIdx.x;
    if (i < NN) {
        int rp = g_rowptr[i] + g_blksums[i >> 10];
        g_rowptr[i] = rp;
        g_pos[i]    = rp;
    }
    if (i == 0) g_rowptr[NN] = TOTE;
}

__global__ void k_fill(const int* __restrict__ src, const int* __restrict__ dst) {
    int i = blockIdx.x * blockDim.x + threadIdx.x;
    if (i >= TOTE) return;
    int s, d;
    if (i < EE) { s = src[i]; d = dst[i]; }
    else        { s = d = i - EE; }
    float w = (1.0f - ALPHA) * g_dinv[s] * g_dinv[d];
    int p = atomicAdd(&g_pos[d], 1);
    g_edata[p] = make_float2(__int_as_float(s), w);
}

// ---------------- GEMM1: h0 = relu(x @ W1 + b1), [N,128]x[128,64] ----------------
__global__ void __launch_bounds__(256) k_gemm1(const float* __restrict__ x,
                                               const float* __restrict__ W1,
                                               const float* __restrict__ b1) {
    __shared__ float Ws[FIN * FHID];
    __shared__ float bs[FHID];
    int tid = threadIdx.x;
    for (int i = tid; i < FIN * FHID / 4; i += 256)
        ((float4*)Ws)[i] = ((const float4*)W1)[i];
    if (tid < FHID) bs[tid] = b1[tid];
    __syncthreads();

    int cg = tid & 7;          // column group: cols cg + 8*j, j<8
    int rsub = tid >> 3;       // 0..31
    int rowBase = blockIdx.x * 128;

    float acc[4][8];
#pragma unroll
    for (int i = 0; i < 4; i++)
#pragma unroll
        for (int j = 0; j < 8; j++) acc[i][j] = 0.f;

    for (int k4 = 0; k4 < FIN / 4; k4++) {
        float4 xv[4];
#pragma unroll
        for (int i = 0; i < 4; i++) {
            int rr = rowBase + rsub + 32 * i;
            xv[i] = (rr < NN) ? __ldg((const float4*)(x + (size_t)rr * FIN) + k4)
                              : make_float4(0.f, 0.f, 0.f, 0.f);
        }
#pragma unroll
        for (int kk = 0; kk < 4; kk++) {
            int k = k4 * 4 + kk;
            float wv[8];
#pragma unroll
            for (int j = 0; j < 8; j++) wv[j] = Ws[k * FHID + cg + 8 * j];
#pragma unroll
            for (int i = 0; i < 4; i++) {
                float xs = (kk == 0) ? xv[i].x : (kk == 1) ? xv[i].y
                          : (kk == 2) ? xv[i].z : xv[i].w;
#pragma unroll
                for (int j = 0; j < 8; j++) acc[i][j] += xs * wv[j];
            }
        }
    }
#pragma unroll
    for (int i = 0; i < 4; i++) {
        int rr = rowBase + rsub + 32 * i;
        if (rr < NN) {
#pragma unroll
            for (int j = 0; j < 8; j++) {
                int c = cg + 8 * j;
                float v = acc[i][j] + bs[c];
                g_h0[(size_t)rr * FHID + c] = fmaxf(v, 0.f);
            }
        }
    }
}

// ---------------- GEMM2: g0 = relu(h @ W2 + b2), [N,64]x[64,40] ----------------
__global__ void __launch_bounds__(256) k_gemm2(const float* __restrict__ xin,
                                               const float* __restrict__ W2,
                                               const float* __restrict__ b2) {
    __shared__ float Ws[FHID * FOUT];
    __shared__ float bs[FOUT];
    int tid = threadIdx.x;
    for (int i = tid; i < FHID * FOUT; i += 256) Ws[i] = W2[i];
    if (tid < FOUT) bs[tid] = b2[tid];
    __syncthreads();

    int cg = tid & 7;          // cols cg + 8*j, j<5
    int rsub = tid >> 3;
    int rowBase = blockIdx.x * 128;

    float acc[4][5];
#pragma unroll
    for (int i = 0; i < 4; i++)
#pragma unroll
        for (int j = 0; j < 5; j++) acc[i][j] = 0.f;

    for (int k4 = 0; k4 < FHID / 4; k4++) {
        float4 xv[4];
#pragma unroll
        for (int i = 0; i < 4; i++) {
            int rr = rowBase + rsub + 32 * i;
            xv[i] = (rr < NN) ? __ldg((const float4*)(xin + (size_t)rr * FHID) + k4)
                              : make_float4(0.f, 0.f, 0.f, 0.f);
        }
#pragma unroll
        for (int kk = 0; kk < 4; kk++) {
            int k = k4 * 4 + kk;
            float wv[5];
#pragma unroll
            for (int j = 0; j < 5; j++) wv[j] = Ws[k * FOUT + cg + 8 * j];
#pragma unroll
            for (int i = 0; i < 4; i++) {
                float xs = (kk == 0) ? xv[i].x : (kk == 1) ? xv[i].y
                          : (kk == 2) ? xv[i].z : xv[i].w;
#pragma unroll
                for (int j = 0; j < 5; j++) acc[i][j] += xs * wv[j];
            }
        }
    }
#pragma unroll
    for (int i = 0; i < 4; i++) {
        int rr = rowBase + rsub + 32 * i;
        if (rr < NN) {
#pragma unroll
            for (int j = 0; j < 5; j++) {
                int c = cg + 8 * j;
                float v = acc[i][j] + bs[c];
                g_h0[(size_t)rr * FOUT + c] = fmaxf(v, 0.f);
            }
        }
    }
}

// ---------------- propagation: out = sum_e w*xin[src] + alpha*h0, warp/node ----------------
template <int F>
__global__ void __launch_bounds__(256) k_prop(const float* __restrict__ xin,
                                              const float* __restrict__ h0,
                                              float* __restrict__ xout) {
    int gw = (blockIdx.x * blockDim.x + threadIdx.x) >> 5;
    int lane = threadIdx.x & 31;
    if (gw >= NN) return;
    int beg = __ldg(&g_rowptr[gw]);
    int end = __ldg(&g_rowptr[gw + 1]);
    bool hi = (F >= 64) || (lane + 32 < F);
    float acc0 = 0.f, acc1 = 0.f;
    for (int j = beg; j < end; j++) {
        float2 e = __ldg(&g_edata[j]);
        int s = __float_as_int(e.x);
        const float* xs = xin + (size_t)s * F;
        acc0 += e.y * __ldg(xs + lane);
        if (F > 32) { if (hi) acc1 += e.y * __ldg(xs + 32 + lane); }
    }
    size_t o = (size_t)gw * F + lane;
    xout[o] = acc0 + ALPHA * __ldg(h0 + o);
    if (F > 32) { if (hi) xout[o + 32] = acc1 + ALPHA * __ldg(h0 + o + 32); }
}

// ---------------- log_softmax over 40 cols, warp/row ----------------
__global__ void __launch_bounds__(256) k_logsoftmax(const float* __restrict__ in,
                                                    float* __restrict__ out) {
    int gw = (blockIdx.x * blockDim.x + threadIdx.x) >> 5;
    int lane = threadIdx.x & 31;
    if (gw >= NN) return;
    const float* r = in + (size_t)gw * FOUT;
    float v0 = r[lane];
    float v1 = (lane < FOUT - 32) ? r[32 + lane] : -INFINITY;
    float m = fmaxf(v0, v1);
#pragma unroll
    for (int off = 16; off > 0; off >>= 1)
        m = fmaxf(m, __shfl_xor_sync(0xFFFFFFFFu, m, off));
    float s = expf(v0 - m) + ((lane < FOUT - 32) ? expf(v1 - m) : 0.f);
#pragma unroll
    for (int off = 16; off > 0; off >>= 1)
        s += __shfl_xor_sync(0xFFFFFFFFu, s, off);
    float lg = m + logf(s);
    out[(size_t)gw * FOUT + lane] = v0 - lg;
    if (lane < FOUT - 32) out[(size_t)gw * FOUT + 32 + lane] = v1 - lg;
}

// ---------------- launch ----------------
extern "C" void kernel_launch(void* const* d_in, const int* in_sizes, int n_in,
                              void* d_out, int out_size) {
    const float* x    = (const float*)d_in[0];
    const int*   edge = (const int*)d_in[1];
    const float* W1   = (const float*)d_in[2];
    const float* b1   = (const float*)d_in[3];
    const float* W2   = (const float*)d_in[4];
    const float* b2   = (const float*)d_in[5];
    const int* src = edge;
    const int* dst = edge + EE;

    float *h0, *A, *B;
    cudaGetSymbolAddress((void**)&h0, g_h0);
    cudaGetSymbolAddress((void**)&A, g_bufA);
    cudaGetSymbolAddress((void**)&B, g_bufB);

    // CSR build
    k_init_cnt<<<(NN + 255) / 256, 256>>>();
    k_deg<<<(EE + 255) / 256, 256>>>(dst);
    k_dinv<<<(NN + 255) / 256, 256>>>();
    k_scan1<<<98, 1024>>>();
    k_scan2<<<1, 128>>>();
    k_scan3<<<(NN + 255) / 256, 256>>>();
    k_fill<<<(TOTE + 255) / 256, 256>>>(src, dst);

    // layer 1
    k_gemm1<<<(NN + 127) / 128, 256>>>(x, W1, b1);
    const int PROP_BLOCKS = (NN * 32 + 255) / 256;
    const float* cur = h0;
    float* nxt = A;
    for (int it = 0; it < KSTEPS; it++) {
        k_prop<FHID><<<PROP_BLOCKS, 256>>>(cur, h0, nxt);
        cur = nxt;
        nxt = (nxt == A) ? B : A;
    }

    // layer 2
    k_gemm2<<<(NN + 127) / 128, 256>>>(cur, W2, b2);   // writes g_h0 (40 cols)
    cur = h0;
    nxt = A;
    for (int it = 0; it < KSTEPS; it++) {
        k_prop<FOUT><<<PROP_BLOCKS, 256>>>(cur, h0, nxt);
        cur = nxt;
        nxt = (nxt == A) ? B : A;
    }

    k_logsoftmax<<<PROP_BLOCKS, 256>>>(cur, (float*)d_out);
}

// round 3
// speedup vs baseline: 1.1570x; 1.1570x over previous
#include <cuda_runtime.h>
#include <math.h>

#define NN   100000
#define EE   1600000
#define TOTE 1700000   // E + N self loops
#define FIN  128
#define FHID 64
#define FOUT 40
#define KSTEPS 10
#define ALPHA 0.1f

// ---------------- scratch (static device globals; no allocation) ----------------
__device__ int    g_cnt[NN];
__device__ int    g_rowptr[NN + 1];
__device__ int    g_pos[NN];
__device__ float  g_dinv[NN];
__device__ float2 g_edata[TOTE];          // {src (bits), weight=0.9*dinv[s]*dinv[d]}
__device__ int    g_blksums[128];
__device__ float4 g_h0v[NN * FHID / 4];   // teleport target (also gemm output)
__device__ float4 g_bufAv[NN * FHID / 4];
__device__ float4 g_bufBv[NN * FHID / 4];

// ---------------- CSR build ----------------
__global__ void k_init_cnt() {
    int i = blockIdx.x * blockDim.x + threadIdx.x;
    if (i < NN) g_cnt[i] = 1;            // self loop
}

__global__ void k_deg(const int* __restrict__ dst) {
    int e = blockIdx.x * blockDim.x + threadIdx.x;
    if (e < EE) atomicAdd(&g_cnt[dst[e]], 1);
}

__global__ void k_scan1() {              // 98 blocks x 1024, also computes dinv
    __shared__ int sh[1024];
    int t = threadIdx.x, b = blockIdx.x;
    int i = b * 1024 + t;
    int v = (i < NN) ? g_cnt[i] : 0;
    if (i < NN) g_dinv[i] = rsqrtf((float)v);
    sh[t] = v;
    __syncthreads();
    for (int off = 1; off < 1024; off <<= 1) {
        int add = (t >= off) ? sh[t - off] : 0;
        __syncthreads();
        sh[t] += add;
        __syncthreads();
    }
    if (i < NN) g_rowptr[i] = sh[t] - v;   // exclusive within block
    if (t == 1023) g_blksums[b] = sh[1023];
}

__global__ void k_scan2() {              // 1 block x 128
    __shared__ int sh[128];
    int t = threadIdx.x;
    int v = (t < 98) ? g_blksums[t] : 0;
    sh[t] = v;
    __syncthreads();
    for (int off = 1; off < 128; off <<= 1) {
        int add = (t >= off) ? sh[t - off] : 0;
        __syncthreads();
        sh[t] += add;
        __syncthreads();
    }
    g_blksums[t] = sh[t] - v;              // exclusive block offsets
}

__global__ void k_scan3() {
    int i = blockIdx.x * blockDim.x + threadIdx.x;
    if (i < NN) {
        int rp = g_rowptr[i] + g_blksums[i >> 10];
        g_rowptr[i] = rp;
        g_pos[i]    = rp;
    }
    if (i == 0) g_rowptr[NN] = TOTE;
}

__global__ void k_fill(const int* __restrict__ src, const int* __restrict__ dst) {
    int i = blockIdx.x * blockDim.x + threadIdx.x;
    if (i >= TOTE) return;
    int s, d;
    if (i < EE) { s = src[i]; d = dst[i]; }
    else        { s = d = i - EE; }
    float w = (1.0f - ALPHA) * g_dinv[s] * g_dinv[d];
    int p = atomicAdd(&g_pos[d], 1);
    g_edata[p] = make_float2(__int_as_float(s), w);
}

// ---------------- GEMM1: h0 = relu(x @ W1 + b1), [N,128]x[128,64] ----------------
// Each thread owns 8 CONTIGUOUS output columns [cg*8, cg*8+8) -> float4 smem
// loads and float4 stores.
__global__ void __launch_bounds__(256) k_gemm1(const float* __restrict__ x,
                                               const float* __restrict__ W1,
                                               const float* __restrict__ b1) {
    __shared__ float Ws[FIN * FHID];
    __shared__ float bs[FHID];
    int tid = threadIdx.x;
    for (int i = tid; i < FIN * FHID / 4; i += 256)
        ((float4*)Ws)[i] = ((const float4*)W1)[i];
    if (tid < FHID) bs[tid] = b1[tid];
    __syncthreads();

    int cg = tid & 7;          // owns cols [cg*8, cg*8+8)
    int rsub = tid >> 3;       // 0..31
    int rowBase = blockIdx.x * 128;
    float* h0 = (float*)g_h0v;

    float acc[4][8];
#pragma unroll
    for (int i = 0; i < 4; i++)
#pragma unroll
        for (int j = 0; j < 8; j++) acc[i][j] = 0.f;

    for (int k4 = 0; k4 < FIN / 4; k4++) {
        float4 xv[4];
#pragma unroll
        for (int i = 0; i < 4; i++) {
            int rr = rowBase + rsub + 32 * i;
            xv[i] = (rr < NN) ? __ldg((const float4*)(x + (size_t)rr * FIN) + k4)
                              : make_float4(0.f, 0.f, 0.f, 0.f);
        }
#pragma unroll
        for (int kk = 0; kk < 4; kk++) {
            int k = k4 * 4 + kk;
            float4 w0 = *(const float4*)&Ws[k * FHID + cg * 8];
            float4 w1 = *(const float4*)&Ws[k * FHID + cg * 8 + 4];
            float wv[8] = {w0.x, w0.y, w0.z, w0.w, w1.x, w1.y, w1.z, w1.w};
#pragma unroll
            for (int i = 0; i < 4; i++) {
                float xs = (kk == 0) ? xv[i].x : (kk == 1) ? xv[i].y
                          : (kk == 2) ? xv[i].z : xv[i].w;
#pragma unroll
                for (int j = 0; j < 8; j++) acc[i][j] += xs * wv[j];
            }
        }
    }
#pragma unroll
    for (int i = 0; i < 4; i++) {
        int rr = rowBase + rsub + 32 * i;
        if (rr < NN) {
            float4 o0, o1;
            o0.x = fmaxf(acc[i][0] + bs[cg * 8 + 0], 0.f);
            o0.y = fmaxf(acc[i][1] + bs[cg * 8 + 1], 0.f);
            o0.z = fmaxf(acc[i][2] + bs[cg * 8 + 2], 0.f);
            o0.w = fmaxf(acc[i][3] + bs[cg * 8 + 3], 0.f);
            o1.x = fmaxf(acc[i][4] + bs[cg * 8 + 4], 0.f);
            o1.y = fmaxf(acc[i][5] + bs[cg * 8 + 5], 0.f);
            o1.z = fmaxf(acc[i][6] + bs[cg * 8 + 6], 0.f);
            o1.w = fmaxf(acc[i][7] + bs[cg * 8 + 7], 0.f);
            float* p = h0 + (size_t)rr * FHID + cg * 8;
            *(float4*)p = o0;
            *(float4*)(p + 4) = o1;
        }
    }
}

// ---------------- GEMM2: g0 = relu(h @ W2 + b2), [N,64]x[64,40] ----------------
__global__ void __launch_bounds__(256) k_gemm2(const float* __restrict__ xin,
                                               const float* __restrict__ W2,
                                               const float* __restrict__ b2) {
    __shared__ float Ws[FHID * FOUT];
    __shared__ float bs[FOUT];
    int tid = threadIdx.x;
    for (int i = tid; i < FHID * FOUT; i += 256) Ws[i] = W2[i];
    if (tid < FOUT) bs[tid] = b2[tid];
    __syncthreads();

    int cg = tid & 7;          // cols cg + 8*j, j<5
    int rsub = tid >> 3;
    int rowBase = blockIdx.x * 128;
    float* h0 = (float*)g_h0v;

    float acc[4][5];
#pragma unroll
    for (int i = 0; i < 4; i++)
#pragma unroll
        for (int j = 0; j < 5; j++) acc[i][j] = 0.f;

    for (int k4 = 0; k4 < FHID / 4; k4++) {
        float4 xv[4];
#pragma unroll
        for (int i = 0; i < 4; i++) {
            int rr = rowBase + rsub + 32 * i;
            xv[i] = (rr < NN) ? __ldg((const float4*)(xin + (size_t)rr * FHID) + k4)
                              : make_float4(0.f, 0.f, 0.f, 0.f);
        }
#pragma unroll
        for (int kk = 0; kk < 4; kk++) {
            int k = k4 * 4 + kk;
            float wv[5];
#pragma unroll
            for (int j = 0; j < 5; j++) wv[j] = Ws[k * FOUT + cg + 8 * j];
#pragma unroll
            for (int i = 0; i < 4; i++) {
                float xs = (kk == 0) ? xv[i].x : (kk == 1) ? xv[i].y
                          : (kk == 2) ? xv[i].z : xv[i].w;
#pragma unroll
                for (int j = 0; j < 5; j++) acc[i][j] += xs * wv[j];
            }
        }
    }
#pragma unroll
    for (int i = 0; i < 4; i++) {
        int rr = rowBase + rsub + 32 * i;
        if (rr < NN) {
#pragma unroll
            for (int j = 0; j < 5; j++) {
                int c = cg + 8 * j;
                float v = acc[i][j] + bs[c];
                h0[(size_t)rr * FOUT + c] = fmaxf(v, 0.f);
            }
        }
    }
}

// ---------------- propagation F=64: warp/node, 2 edge-groups x 16 lanes x float4 ----------------
__global__ void __launch_bounds__(256) k_prop64(const float4* __restrict__ xin,
                                                const float4* __restrict__ h0,
                                                float4* __restrict__ xout) {
    int gw = (blockIdx.x * blockDim.x + threadIdx.x) >> 5;
    int lane = threadIdx.x & 31;
    if (gw >= NN) return;
    int beg = __ldg(&g_rowptr[gw]);
    int end = __ldg(&g_rowptr[gw + 1]);
    int grp = lane >> 4;       // 0,1
    int sub = lane & 15;       // float4 slot within row (16*4 = 64 floats)
    float4 acc = make_float4(0.f, 0.f, 0.f, 0.f);
#pragma unroll 2
    for (int j = beg + grp; j < end; j += 2) {
        float2 e = __ldg(&g_edata[j]);
        int s = __float_as_int(e.x);
        float4 xv = __ldg(xin + (size_t)s * 16 + sub);
        acc.x += e.y * xv.x;
        acc.y += e.y * xv.y;
        acc.z += e.y * xv.z;
        acc.w += e.y * xv.w;
    }
    acc.x += __shfl_down_sync(0xFFFFFFFFu, acc.x, 16);
    acc.y += __shfl_down_sync(0xFFFFFFFFu, acc.y, 16);
    acc.z += __shfl_down_sync(0xFFFFFFFFu, acc.z, 16);
    acc.w += __shfl_down_sync(0xFFFFFFFFu, acc.w, 16);
    if (grp == 0) {
        float4 t = __ldg(h0 + (size_t)gw * 16 + sub);
        acc.x += ALPHA * t.x;
        acc.y += ALPHA * t.y;
        acc.z += ALPHA * t.z;
        acc.w += ALPHA * t.w;
        xout[(size_t)gw * 16 + sub] = acc;
    }
}

// ---------------- propagation F=40: warp/node, 3 edge-groups x 10 lanes x float4 ----------------
__device__ __forceinline__ float4 prop40_body(int gw, int lane, int grp, int sub,
                                              const float* __restrict__ xin,
                                              const float* __restrict__ h0) {
    int beg = __ldg(&g_rowptr[gw]);
    int end = __ldg(&g_rowptr[gw + 1]);
    float4 acc = make_float4(0.f, 0.f, 0.f, 0.f);
    if (grp < 3) {
#pragma unroll 2
        for (int j = beg + grp; j < end; j += 3) {
            float2 e = __ldg(&g_edata[j]);
            int s = __float_as_int(e.x);
            float4 xv = __ldg((const float4*)(xin + (size_t)s * FOUT) + sub);
            acc.x += e.y * xv.x;
            acc.y += e.y * xv.y;
            acc.z += e.y * xv.z;
            acc.w += e.y * xv.w;
        }
    }
    float t1x = __shfl_sync(0xFFFFFFFFu, acc.x, lane + 10 < 32 ? lane + 10 : lane);
    float t1y = __shfl_sync(0xFFFFFFFFu, acc.y, lane + 10 < 32 ? lane + 10 : lane);
    float t1z = __shfl_sync(0xFFFFFFFFu, acc.z, lane + 10 < 32 ? lane + 10 : lane);
    float t1w = __shfl_sync(0xFFFFFFFFu, acc.w, lane + 10 < 32 ? lane + 10 : lane);
    float t2x = __shfl_sync(0xFFFFFFFFu, acc.x, lane + 20 < 32 ? lane + 20 : lane);
    float t2y = __shfl_sync(0xFFFFFFFFu, acc.y, lane + 20 < 32 ? lane + 20 : lane);
    float t2z = __shfl_sync(0xFFFFFFFFu, acc.z, lane + 20 < 32 ? lane + 20 : lane);
    float t2w = __shfl_sync(0xFFFFFFFFu, acc.w, lane + 20 < 32 ? lane + 20 : lane);
    acc.x += t1x + t2x;
    acc.y += t1y + t2y;
    acc.z += t1z + t2z;
    acc.w += t1w + t2w;
    if (grp == 0) {
        float4 t = __ldg((const float4*)(h0 + (size_t)gw * FOUT) + sub);
        acc.x += ALPHA * t.x;
        acc.y += ALPHA * t.y;
        acc.z += ALPHA * t.z;
        acc.w += ALPHA * t.w;
    }
    return acc;
}

__global__ void __launch_bounds__(256) k_prop40(const float* __restrict__ xin,
                                                const float* __restrict__ h0,
                                                float* __restrict__ xout) {
    int gw = (blockIdx.x * blockDim.x + threadIdx.x) >> 5;
    int lane = threadIdx.x & 31;
    if (gw >= NN) return;
    int grp = lane / 10;
    int sub = lane - grp * 10;
    float4 acc = prop40_body(gw, lane, grp, sub, xin, h0);
    if (grp == 0)
        ((float4*)(xout + (size_t)gw * FOUT))[sub] = acc;
}

// final step fused with log_softmax (40 cols live in lanes 0..9 x float4)
__global__ void __launch_bounds__(256) k_prop40_lsm(const float* __restrict__ xin,
                                                    const float* __restrict__ h0,
                                                    float* __restrict__ out) {
    int gw = (blockIdx.x * blockDim.x + threadIdx.x) >> 5;
    int lane = threadIdx.x & 31;
    if (gw >= NN) return;
    int grp = lane / 10;
    int sub = lane - grp * 10;
    float4 v = prop40_body(gw, lane, grp, sub, xin, h0);
    bool act = (grp == 0);
    float m = act ? fmaxf(fmaxf(v.x, v.y), fmaxf(v.z, v.w)) : -INFINITY;
#pragma unroll
    for (int off = 16; off > 0; off >>= 1)
        m = fmaxf(m, __shfl_xor_sync(0xFFFFFFFFu, m, off));
    float s = act ? (expf(v.x - m) + expf(v.y - m) + expf(v.z - m) + expf(v.w - m)) : 0.f;
#pragma unroll
    for (int off = 16; off > 0; off >>= 1)
        s += __shfl_xor_sync(0xFFFFFFFFu, s, off);
    float lg = m + logf(s);
    if (act) {
        float4 o = make_float4(v.x - lg, v.y - lg, v.z - lg, v.w - lg);
        ((float4*)(out + (size_t)gw * FOUT))[sub] = o;
    }
}

// ---------------- launch ----------------
extern "C" void kernel_launch(void* const* d_in, const int* in_sizes, int n_in,
                              void* d_out, int out_size) {
    const float* x    = (const float*)d_in[0];
    const int*   edge = (const int*)d_in[1];
    const float* W1   = (const float*)d_in[2];
    const float* b1   = (const float*)d_in[3];
    const float* W2   = (const float*)d_in[4];
    const float* b2   = (const float*)d_in[5];
    const int* src = edge;
    const int* dst = edge + EE;

    float4 *h0, *A, *B;
    cudaGetSymbolAddress((void**)&h0, g_h0v);
    cudaGetSymbolAddress((void**)&A, g_bufAv);
    cudaGetSymbolAddress((void**)&B, g_bufBv);

    // CSR build
    k_init_cnt<<<(NN + 255) / 256, 256>>>();
    k_deg<<<(EE + 255) / 256, 256>>>(dst);
    k_scan1<<<98, 1024>>>();
    k_scan2<<<1, 128>>>();
    k_scan3<<<(NN + 255) / 256, 256>>>();
    k_fill<<<(TOTE + 255) / 256, 256>>>(src, dst);

    // layer 1
    k_gemm1<<<(NN + 127) / 128, 256>>>(x, W1, b1);
    const int PROP_BLOCKS = (NN * 32 + 255) / 256;
    const float4* cur = h0;
    float4* nxt = A;
    for (int it = 0; it < KSTEPS; it++) {
        k_prop64<<<PROP_BLOCKS, 256>>>(cur, h0, nxt);
        cur = nxt;
        nxt = (nxt == A) ? B : A;
    }

    // layer 2
    k_gemm2<<<(NN + 127) / 128, 256>>>((const float*)cur, W2, b2);  // writes h0, 40 cols
    const float* cur2 = (const float*)h0;
    float* nxt2 = (float*)A;
    for (int it = 0; it < KSTEPS - 1; it++) {
        k_prop40<<<PROP_BLOCKS, 256>>>(cur2, (const float*)h0, nxt2);
        cur2 = nxt2;
        nxt2 = (nxt2 == (float*)A) ? (float*)B : (float*)A;
    }
    k_prop40_lsm<<<PROP_BLOCKS, 256>>>(cur2, (const float*)h0, (float*)d_out);
}

// round 6
// speedup vs baseline: 2.0742x; 1.7928x over previous
#include <cuda_runtime.h>
#include <cuda_fp16.h>
#include <math.h>

#define NN   100000
#define EE   1600000
#define TOTE 1700000   // E + N self loops
#define FIN  128
#define FHID 64
#define FOUT 40
#define KSTEPS 10
#define ALPHA 0.1f

// ---------------- scratch (static device globals; no allocation) ----------------
__device__ int   g_cnt[NN];
__device__ int   g_rowptr[NN + 1];
__device__ int   g_pos[NN];
__device__ float g_dinv[NN];
__device__ int   g_esrc[TOTE];           // src index only (weights folded into iterate)
__device__ int   g_blksums[128];
// half-precision node-feature buffers, 128B per row (max F=64 halves)
__device__ uint4 g_h0[NN * 8];           // teleport target
__device__ uint4 g_bufA[NN * 8];
__device__ uint4 g_bufB[NN * 8];

// ---------------- CSR build ----------------
__global__ void k_init_cnt() {
    int i = blockIdx.x * blockDim.x + threadIdx.x;
    if (i < NN) g_cnt[i] = 1;            // self loop
}

__global__ void k_deg(const int* __restrict__ dst) {
    int e = blockIdx.x * blockDim.x + threadIdx.x;
    if (e < EE) atomicAdd(&g_cnt[dst[e]], 1);
}

__global__ void k_scan1() {              // 98 blocks x 1024, also computes dinv
    __shared__ int sh[1024];
    int t = threadIdx.x, b = blockIdx.x;
    int i = b * 1024 + t;
    int v = (i < NN) ? g_cnt[i] : 0;
    if (i < NN) g_dinv[i] = rsqrtf((float)v);
    sh[t] = v;
    __syncthreads();
    for (int off = 1; off < 1024; off <<= 1) {
        int add = (t >= off) ? sh[t - off] : 0;
        __syncthreads();
        sh[t] += add;
        __syncthreads();
    }
    if (i < NN) g_rowptr[i] = sh[t] - v;   // exclusive within block
    if (t == 1023) g_blksums[b] = sh[1023];
}

__global__ void k_scan2() {              // 1 block x 128
    __shared__ int sh[128];
    int t = threadIdx.x;
    int v = (t < 98) ? g_blksums[t] : 0;
    sh[t] = v;
    __syncthreads();
    for (int off = 1; off < 128; off <<= 1) {
        int add = (t >= off) ? sh[t - off] : 0;
        __syncthreads();
        sh[t] += add;
        __syncthreads();
    }
    g_blksums[t] = sh[t] - v;              // exclusive block offsets
}

__global__ void k_scan3() {
    int i = blockIdx.x * blockDim.x + threadIdx.x;
    if (i < NN) {
        int rp = g_rowptr[i] + g_blksums[i >> 10];
        g_rowptr[i] = rp;
        g_pos[i]    = rp;
    }
    if (i == 0) g_rowptr[NN] = TOTE;
}

__global__ void k_fill(const int* __restrict__ src, const int* __restrict__ dst) {
    int i = blockIdx.x * blockDim.x + threadIdx.x;
    if (i >= TOTE) return;
    int s, d;
    if (i < EE) { s = src[i]; d = dst[i]; }
    else        { s = d = i - EE; }
    int p = atomicAdd(&g_pos[d], 1);
    g_esrc[p] = s;
}

// ---------------- GEMM1: h0 = relu(x@W1+b1); z0 = dinv*h0 (both half) ----------------
__global__ void __launch_bounds__(256) k_gemm1(const float* __restrict__ x,
                                               const float* __restrict__ W1,
                                               const float* __restrict__ b1) {
    __shared__ float Ws[FIN * FHID];
    __shared__ float bs[FHID];
    int tid = threadIdx.x;
    for (int i = tid; i < FIN * FHID / 4; i += 256)
        ((float4*)Ws)[i] = ((const float4*)W1)[i];
    if (tid < FHID) bs[tid] = b1[tid];
    __syncthreads();

    int cg = tid & 7;          // owns cols [cg*8, cg*8+8)
    int rsub = tid >> 3;       // 0..31
    int rowBase = blockIdx.x * 128;

    float acc[4][8];
#pragma unroll
    for (int i = 0; i < 4; i++)
#pragma unroll
        for (int j = 0; j < 8; j++) acc[i][j] = 0.f;

    for (int k4 = 0; k4 < FIN / 4; k4++) {
        float4 xv[4];
#pragma unroll
        for (int i = 0; i < 4; i++) {
            int rr = rowBase + rsub + 32 * i;
            xv[i] = (rr < NN) ? __ldg((const float4*)(x + (size_t)rr * FIN) + k4)
                              : make_float4(0.f, 0.f, 0.f, 0.f);
        }
#pragma unroll
        for (int kk = 0; kk < 4; kk++) {
            int k = k4 * 4 + kk;
            float4 w0 = *(const float4*)&Ws[k * FHID + cg * 8];
            float4 w1 = *(const float4*)&Ws[k * FHID + cg * 8 + 4];
            float wv[8] = {w0.x, w0.y, w0.z, w0.w, w1.x, w1.y, w1.z, w1.w};
#pragma unroll
            for (int i = 0; i < 4; i++) {
                float xs = (kk == 0) ? xv[i].x : (kk == 1) ? xv[i].y
                          : (kk == 2) ? xv[i].z : xv[i].w;
#pragma unroll
                for (int j = 0; j < 8; j++) acc[i][j] += xs * wv[j];
            }
        }
    }
#pragma unroll
    for (int i = 0; i < 4; i++) {
        int rr = rowBase + rsub + 32 * i;
        if (rr < NN) {
            float dv = g_dinv[rr];
            float r[8];
#pragma unroll
            for (int j = 0; j < 8; j++) r[j] = fmaxf(acc[i][j] + bs[cg * 8 + j], 0.f);
            uint4 oh, oz;
            *(__half2*)&oh.x = __floats2half2_rn(r[0], r[1]);
            *(__half2*)&oh.y = __floats2half2_rn(r[2], r[3]);
            *(__half2*)&oh.z = __floats2half2_rn(r[4], r[5]);
            *(__half2*)&oh.w = __floats2half2_rn(r[6], r[7]);
            *(__half2*)&oz.x = __floats2half2_rn(dv * r[0], dv * r[1]);
            *(__half2*)&oz.y = __floats2half2_rn(dv * r[2], dv * r[3]);
            *(__half2*)&oz.z = __floats2half2_rn(dv * r[4], dv * r[5]);
            *(__half2*)&oz.w = __floats2half2_rn(dv * r[6], dv * r[7]);
            g_h0[(size_t)rr * 8 + cg]   = oh;
            g_bufA[(size_t)rr * 8 + cg] = oz;
        }
    }
}

// ---------------- GEMM2: h2 = relu(x10@W2+b2); writes h0_40 and z (half) ----------------
__global__ void __launch_bounds__(256) k_gemm2(const __half* __restrict__ xin,
                                               const float* __restrict__ W2,
                                               const float* __restrict__ b2,
                                               __half* __restrict__ h0o,
                                               __half* __restrict__ zo) {
    __shared__ float Ws[FHID * FOUT];
    __shared__ float bs[FOUT];
    int tid = threadIdx.x;
    for (int i = tid; i < FHID * FOUT; i += 256) Ws[i] = W2[i];
    if (tid < FOUT) bs[tid] = b2[tid];
    __syncthreads();

    int cg = tid & 7;          // cols cg + 8*j, j<5
    int rsub = tid >> 3;
    int rowBase = blockIdx.x * 128;

    float acc[4][5];
#pragma unroll
    for (int i = 0; i < 4; i++)
#pragma unroll
        for (int j = 0; j < 5; j++) acc[i][j] = 0.f;

    for (int k8 = 0; k8 < FHID / 8; k8++) {
        float xf[4][8];
#pragma unroll
        for (int i = 0; i < 4; i++) {
            int rr = rowBase + rsub + 32 * i;
            uint4 v = (rr < NN) ? __ldg((const uint4*)xin + (size_t)rr * 8 + k8)
                                : make_uint4(0u, 0u, 0u, 0u);
            float2 f0 = __half22float2(*(__half2*)&v.x);
            float2 f1 = __half22float2(*(__half2*)&v.y);
            float2 f2 = __half22float2(*(__half2*)&v.z);
            float2 f3 = __half22float2(*(__half2*)&v.w);
            xf[i][0] = f0.x; xf[i][1] = f0.y; xf[i][2] = f1.x; xf[i][3] = f1.y;
            xf[i][4] = f2.x; xf[i][5] = f2.y; xf[i][6] = f3.x; xf[i][7] = f3.y;
        }
#pragma unroll
        for (int kk = 0; kk < 8; kk++) {
            int k = k8 * 8 + kk;
            float wv[5];
#pragma unroll
            for (int j = 0; j < 5; j++) wv[j] = Ws[k * FOUT + cg + 8 * j];
#pragma unroll
            for (int i = 0; i < 4; i++)
#pragma unroll
                for (int j = 0; j < 5; j++) acc[i][j] += xf[i][kk] * wv[j];
        }
    }
#pragma unroll
    for (int i = 0; i < 4; i++) {
        int rr = rowBase + rsub + 32 * i;
        if (rr < NN) {
            float dv = g_dinv[rr];
#pragma unroll
            for (int j = 0; j < 5; j++) {
                int c = cg + 8 * j;
                float v = fmaxf(acc[i][j] + bs[c], 0.f);
                h0o[(size_t)rr * FOUT + c] = __float2half_rn(v);
                zo[(size_t)rr * FOUT + c]  = __float2half_rn(dv * v);
            }
        }
    }
}

// ---------------- prop F=64 (half): z'[d] = dinv_d*(0.9*dinv_d*sum z[s] + 0.1*h0[d]) ----------------
template <bool FINAL>
__global__ void __launch_bounds__(256) k_prop64h(const uint2* __restrict__ zin,
                                                 const uint2* __restrict__ h0,
                                                 uint2* __restrict__ zout) {
    int gw = (blockIdx.x * blockDim.x + threadIdx.x) >> 5;
    int lane = threadIdx.x & 31;
    if (gw >= NN) return;
    int beg = __ldg(&g_rowptr[gw]);
    int end = __ldg(&g_rowptr[gw + 1]);
    int grp = lane >> 4;       // 0,1
    int sub = lane & 15;       // uint2 (4-half) slot within 64-half row
    float ax = 0.f, ay = 0.f, az = 0.f, aw = 0.f;
#pragma unroll 4
    for (int j = beg + grp; j < end; j += 2) {
        int s = __ldg(&g_esrc[j]);
        uint2 v = __ldg(zin + (size_t)s * 16 + sub);
        float2 f0 = __half22float2(*(__half2*)&v.x);
        float2 f1 = __half22float2(*(__half2*)&v.y);
        ax += f0.x; ay += f0.y; az += f1.x; aw += f1.y;
    }
    ax += __shfl_down_sync(0xFFFFFFFFu, ax, 16);
    ay += __shfl_down_sync(0xFFFFFFFFu, ay, 16);
    az += __shfl_down_sync(0xFFFFFFFFu, az, 16);
    aw += __shfl_down_sync(0xFFFFFFFFu, aw, 16);
    if (grp == 0) {
        float dv = __ldg(&g_dinv[gw]);
        uint2 hv = __ldg(h0 + (size_t)gw * 16 + sub);
        float2 h0a = __half22float2(*(__half2*)&hv.x);
        float2 h0b = __half22float2(*(__half2*)&hv.y);
        float c = (1.0f - ALPHA) * dv;
        float x0 = c * ax + ALPHA * h0a.x;
        float x1 = c * ay + ALPHA * h0a.y;
        float x2 = c * az + ALPHA * h0b.x;
        float x3 = c * aw + ALPHA * h0b.y;
        float sc = FINAL ? 1.0f : dv;
        uint2 o;
        *(__half2*)&o.x = __floats2half2_rn(sc * x0, sc * x1);
        *(__half2*)&o.y = __floats2half2_rn(sc * x2, sc * x3);
        zout[(size_t)gw * 16 + sub] = o;
    }
}

// ---------------- prop F=40 (half): 3 edge-groups x 10 lanes x 4 halves ----------------
__device__ __forceinline__ float4 prop40_acc(int gw, int lane, int grp, int sub,
                                             const uint2* __restrict__ zin) {
    int beg = __ldg(&g_rowptr[gw]);
    int end = __ldg(&g_rowptr[gw + 1]);
    float4 a = make_float4(0.f, 0.f, 0.f, 0.f);
    if (grp < 3) {
#pragma unroll 4
        for (int j = beg + grp; j < end; j += 3) {
            int s = __ldg(&g_esrc[j]);
            uint2 v = __ldg(zin + (size_t)s * 10 + sub);
            float2 f0 = __half22float2(*(__half2*)&v.x);
            float2 f1 = __half22float2(*(__half2*)&v.y);
            a.x += f0.x; a.y += f0.y; a.z += f1.x; a.w += f1.y;
        }
    }
    int l1 = lane + 10 < 32 ? lane + 10 : lane;
    int l2 = lane + 20 < 32 ? lane + 20 : lane;
    float t1x = __shfl_sync(0xFFFFFFFFu, a.x, l1);
    float t1y = __shfl_sync(0xFFFFFFFFu, a.y, l1);
    float t1z = __shfl_sync(0xFFFFFFFFu, a.z, l1);
    float t1w = __shfl_sync(0xFFFFFFFFu, a.w, l1);
    float t2x = __shfl_sync(0xFFFFFFFFu, a.x, l2);
    float t2y = __shfl_sync(0xFFFFFFFFu, a.y, l2);
    float t2z = __shfl_sync(0xFFFFFFFFu, a.z, l2);
    float t2w = __shfl_sync(0xFFFFFFFFu, a.w, l2);
    a.x += t1x + t2x; a.y += t1y + t2y; a.z += t1z + t2z; a.w += t1w + t2w;
    return a;
}

__global__ void __launch_bounds__(256) k_prop40h(const uint2* __restrict__ zin,
                                                 const uint2* __restrict__ h0,
                                                 uint2* __restrict__ zout) {
    int gw = (blockIdx.x * blockDim.x + threadIdx.x) >> 5;
    int lane = threadIdx.x & 31;
    if (gw >= NN) return;
    int grp = lane / 10;
    int sub = lane - grp * 10;
    float4 a = prop40_acc(gw, lane, grp, sub, zin);
    if (grp == 0) {
        float dv = __ldg(&g_dinv[gw]);
        uint2 hv = __ldg(h0 + (size_t)gw * 10 + sub);
        float2 h0a = __half22float2(*(__half2*)&hv.x);
        float2 h0b = __half22float2(*(__half2*)&hv.y);
        float c = (1.0f - ALPHA) * dv;
        float x0 = dv * (c * a.x + ALPHA * h0a.x);
        float x1 = dv * (c * a.y + ALPHA * h0a.y);
        float x2 = dv * (c * a.z + ALPHA * h0b.x);
        float x3 = dv * (c * a.w + ALPHA * h0b.y);
        uint2 o;
        *(__half2*)&o.x = __floats2half2_rn(x0, x1);
        *(__half2*)&o.y = __floats2half2_rn(x2, x3);
        zout[(size_t)gw * 10 + sub] = o;
    }
}

// final F=40 step fused with log_softmax, fp32 output
__global__ void __launch_bounds__(256) k_prop40_lsm(const uint2* __restrict__ zin,
                                                    const uint2* __restrict__ h0,
                                                    float* __restrict__ out) {
    int gw = (blockIdx.x * blockDim.x + threadIdx.x) >> 5;
    int lane = threadIdx.x & 31;
    if (gw >= NN) return;
    int grp = lane / 10;
    int sub = lane - grp * 10;
    float4 a = prop40_acc(gw, lane, grp, sub, zin);
    float dv = __ldg(&g_dinv[gw]);
    float4 v = make_float4(-INFINITY, -INFINITY, -INFINITY, -INFINITY);
    bool act = (grp == 0);
    if (act) {
        uint2 hv = __ldg(h0 + (size_t)gw * 10 + sub);
        float2 h0a = __half22float2(*(__half2*)&hv.x);
        float2 h0b = __half22float2(*(__half2*)&hv.y);
        float c = (1.0f - ALPHA) * dv;
        v.x = c * a.x + ALPHA * h0a.x;
        v.y = c * a.y + ALPHA * h0a.y;
        v.z = c * a.z + ALPHA * h0b.x;
        v.w = c * a.w + ALPHA * h0b.y;
    }
    float m = act ? fmaxf(fmaxf(v.x, v.y), fmaxf(v.z, v.w)) : -INFINITY;
#pragma unroll
    for (int off = 16; off > 0; off >>= 1)
        m = fmaxf(m, __shfl_xor_sync(0xFFFFFFFFu, m, off));
    float s = act ? (expf(v.x - m) + expf(v.y - m) + expf(v.z - m) + expf(v.w - m)) : 0.f;
#pragma unroll
    for (int off = 16; off > 0; off >>= 1)
        s += __shfl_xor_sync(0xFFFFFFFFu, s, off);
    float lg = m + logf(s);
    if (act) {
        float4 o = make_float4(v.x - lg, v.y - lg, v.z - lg, v.w - lg);
        ((float4*)(out + (size_t)gw * FOUT))[sub] = o;
    }
}

// ---------------- launch ----------------
extern "C" void kernel_launch(void* const* d_in, const int* in_sizes, int n_in,
                              void* d_out, int out_size) {
    const float* x    = (const float*)d_in[0];
    const int*   edge = (const int*)d_in[1];
    const float* W1   = (const float*)d_in[2];
    const float* b1   = (const float*)d_in[3];
    const float* W2   = (const float*)d_in[4];
    const float* b2   = (const float*)d_in[5];
    const int* src = edge;
    const int* dst = edge + EE;

    uint2 *h0, *A, *B;
    cudaGetSymbolAddress((void**)&h0, g_h0);
    cudaGetSymbolAddress((void**)&A, g_bufA);
    cudaGetSymbolAddress((void**)&B, g_bufB);

    // CSR build
    k_init_cnt<<<(NN + 255) / 256, 256>>>();
    k_deg<<<(EE + 255) / 256, 256>>>(dst);
    k_scan1<<<98, 1024>>>();
    k_scan2<<<1, 128>>>();
    k_scan3<<<(NN + 255) / 256, 256>>>();
    k_fill<<<(TOTE + 255) / 256, 256>>>(src, dst);

    const int PROP_BLOCKS = (NN * 32 + 255) / 256;

    // layer 1: GEMM writes h0 (half) and z0 -> bufA (half, dinv-scaled)
    k_gemm1<<<(NN + 127) / 128, 256>>>(x, W1, b1);
    const uint2* cur = A;
    uint2* nxt = B;
    for (int it = 0; it < KSTEPS - 1; it++) {
        k_prop64h<false><<<PROP_BLOCKS, 256>>>(cur, h0, nxt);
        const uint2* t = nxt; nxt = (uint2*)cur; cur = t;
    }
    k_prop64h<true><<<PROP_BLOCKS, 256>>>(cur, h0, nxt);   // unscaled x10 -> nxt

    // layer 2: GEMM reads x10 (half), writes h0_40 (g_h0) and z -> other buffer
    uint2* x10 = nxt;
    uint2* zb  = (x10 == A) ? B : A;
    k_gemm2<<<(NN + 127) / 128, 256>>>((const __half*)x10, W2, b2,
                                       (__half*)h0, (__half*)zb);
    cur = zb;
    nxt = x10;
    for (int it = 0; it < KSTEPS - 1; it++) {
        k_prop40h<<<PROP_BLOCKS, 256>>>(cur, h0, nxt);
        const uint2* t = nxt; nxt = (uint2*)cur; cur = t;
    }
    k_prop40_lsm<<<PROP_BLOCKS, 256>>>(cur, h0, (float*)d_out);
}